// round 2
// baseline (speedup 1.0000x reference)
#include <cuda_runtime.h>
#include <cstdint>
#include <cstddef>

// ----------------------------------------------------------------------------
// Persistent cluster RNN:
//   a <- a + W2^T tanh(W1^T [x_t; a] + b1) + b2,  512 steps.
// Grid: 128 CTAs = 32 clusters x 4. Cluster owns 8 batch rows.
// CTA (cluster rank c) owns hidden slice [128c, 128c+128) with fp32 weight
// slices resident in smem. Cross-CTA state reduction goes through L2
// (__stcg/__ldcg on a __device__ scratch buffer), 1 cluster barrier / step.
// ----------------------------------------------------------------------------

#define T_STEPS  512
#define DIN      128
#define DST      128
#define DHID     512
#define NCL      32     // clusters
#define CSZ      4      // CTAs per cluster (hidden split)
#define ROWS     8      // batch rows per cluster
#define NTHREADS 256

// double-buffered per-rank partial states (1 MB, static device scratch)
__device__ float g_pstate[2][NCL][CSZ][ROWS][DST];

// smem layout (floats):
//   W1s [256][128] @ 0        (131072 B)
//   W2s [128][128] @ 32768    ( 65536 B)
//   a_s [  8][128] @ 49152    (  4096 B)
//   xh  [  8][128] @ 50176    (  4096 B)   x_t, then reused for h
//   hp  [4][8][128]@ 51200    ( 16384 B)   k-split partials
#define SMEM_FLOATS 55296     // 221184 bytes

static __device__ __forceinline__ float4 f4add(float4 a, float4 b) {
    return make_float4(a.x + b.x, a.y + b.y, a.z + b.z, a.w + b.w);
}

__global__ void __cluster_dims__(CSZ, 1, 1) __launch_bounds__(NTHREADS, 1)
rnn_kernel(const float* __restrict__ x,  const float* __restrict__ a0,
           const float* __restrict__ W1, const float* __restrict__ b1,
           const float* __restrict__ W2, const float* __restrict__ b2,
           float* __restrict__ out)
{
    extern __shared__ float sm[];
    float* W1s = sm;            // [256][128] rows = global k (x:0..127, a:128..255)
    float* W2s = sm + 32768;    // [128][128] rows = local hidden j
    float* a_s = sm + 49152;    // [8][128]
    float* xh  = sm + 50176;    // [8][128]  x_t then h
    float* hp  = sm + 51200;    // [4][8][128]

    const int tid   = threadIdx.x;
    const int lane  = tid & 31;
    const int wid   = tid >> 5;
    const int bx    = blockIdx.x;
    const int crank = bx & (CSZ - 1);
    const int gcl   = bx >> 2;
    const int rowbase = gcl * ROWS;
    const int jbase   = crank * 128;

    // ---- load resident weight slices ----
    for (int i = tid; i < 256 * 128; i += NTHREADS)
        W1s[i] = W1[(i >> 7) * DHID + jbase + (i & 127)];
    for (int i = tid; i < 128 * 128; i += NTHREADS)
        W2s[i] = W2[jbase * DST + i];
    for (int i = tid; i < ROWS * DST; i += NTHREADS)
        a_s[i] = a0[rowbase * DST + i];

    // combine-stage mapping: warp w handles row w, lane handles 4 consecutive cols
    const int crow = wid;
    const int cj   = lane * 4;
    const float4 rb1 = *(const float4*)(b1 + jbase + cj);
    const float4 rb2 = *(const float4*)(b2 + cj);

    // GEMM warp roles: row-group (4 rows) x K-chunk
    const int rg = (wid & 1) * 4;
    const int kc = wid >> 1;           // 0..3

    // x prefetch (row crow, cols cj..cj+3)
    const float* xptr = x + (size_t)(rowbase + crow) * (size_t)(T_STEPS * DIN) + cj;
    float4 xr = *(const float4*)(xptr);

    float4 myp = make_float4(0.f, 0.f, 0.f, 0.f);   // my partial state (kept in regs)

    __syncthreads();

    for (int t = 0; t < T_STEPS; ++t) {
        // ---- apply step t-1 state: a += sum of partials + b2 ----
        if (t > 0) {
            const int pb = (t - 1) & 1;
            float4 acc = myp;
            #pragma unroll
            for (int r = 0; r < CSZ; ++r) {
                if (r == crank) continue;
                float4 v = __ldcg((const float4*)&g_pstate[pb][gcl][r][crow][cj]);
                acc = f4add(acc, v);
            }
            float4 av = *(float4*)(a_s + crow * DST + cj);
            av.x += acc.x + rb2.x;  av.y += acc.y + rb2.y;
            av.z += acc.z + rb2.z;  av.w += acc.w + rb2.w;
            *(float4*)(a_s + crow * DST + cj) = av;
        }

        // stage x_t, prefetch x_{t+1}
        *(float4*)(xh + crow * DIN + cj) = xr;
        if (t + 1 < T_STEPS) xr = *(const float4*)(xptr + (size_t)(t + 1) * DIN);
        __syncthreads();

        // ---- G1: preact partial over K-chunk kc (64 ks), 4 rows x 128 j ----
        {
            float4 c0 = make_float4(0.f,0.f,0.f,0.f), c1 = c0, c2 = c0, c3 = c0;
            const float* src = (kc < 2) ? xh : a_s;        // k<128 -> x, else a
            const float* s0 = src + (rg + 0) * 128 + ((kc & 1) * 64);
            const float* s1 = s0 + 128;
            const float* s2 = s0 + 256;
            const float* s3 = s0 + 384;
            const float* wr = W1s + (kc * 64) * 128 + cj;
            #pragma unroll 4
            for (int kk = 0; kk < 64; ++kk) {
                const float v0 = s0[kk], v1 = s1[kk], v2 = s2[kk], v3 = s3[kk];
                const float4 w = *(const float4*)(wr + kk * 128);
                c0.x += v0 * w.x; c0.y += v0 * w.y; c0.z += v0 * w.z; c0.w += v0 * w.w;
                c1.x += v1 * w.x; c1.y += v1 * w.y; c1.z += v1 * w.z; c1.w += v1 * w.w;
                c2.x += v2 * w.x; c2.y += v2 * w.y; c2.z += v2 * w.z; c2.w += v2 * w.w;
                c3.x += v3 * w.x; c3.y += v3 * w.y; c3.z += v3 * w.z; c3.w += v3 * w.w;
            }
            float* hpb = hp + kc * 1024 + rg * 128 + cj;
            *(float4*)(hpb)       = c0;
            *(float4*)(hpb + 128) = c1;
            *(float4*)(hpb + 256) = c2;
            *(float4*)(hpb + 384) = c3;
        }
        __syncthreads();

        // ---- combine K-chunks + bias + tanh -> h (into xh buffer) ----
        {
            const float* hb = hp + crow * 128 + cj;
            float4 p0 = *(const float4*)(hb);
            float4 p1 = *(const float4*)(hb + 1024);
            float4 p2 = *(const float4*)(hb + 2048);
            float4 p3 = *(const float4*)(hb + 3072);
            float4 h;
            h.x = tanhf(p0.x + p1.x + p2.x + p3.x + rb1.x);
            h.y = tanhf(p0.y + p1.y + p2.y + p3.y + rb1.y);
            h.z = tanhf(p0.z + p1.z + p2.z + p3.z + rb1.z);
            h.w = tanhf(p0.w + p1.w + p2.w + p3.w + rb1.w);
            *(float4*)(xh + crow * 128 + cj) = h;
        }
        __syncthreads();

        // ---- G2: state partial over local-j chunk kc (32 js), 4 rows x 128 s ----
        {
            float4 c0 = make_float4(0.f,0.f,0.f,0.f), c1 = c0, c2 = c0, c3 = c0;
            const float* s0 = xh + (rg + 0) * 128 + kc * 32;
            const float* s1 = s0 + 128;
            const float* s2 = s0 + 256;
            const float* s3 = s0 + 384;
            const float* wr = W2s + (kc * 32) * 128 + cj;
            #pragma unroll 4
            for (int jj = 0; jj < 32; ++jj) {
                const float v0 = s0[jj], v1 = s1[jj], v2 = s2[jj], v3 = s3[jj];
                const float4 w = *(const float4*)(wr + jj * 128);
                c0.x += v0 * w.x; c0.y += v0 * w.y; c0.z += v0 * w.z; c0.w += v0 * w.w;
                c1.x += v1 * w.x; c1.y += v1 * w.y; c1.z += v1 * w.z; c1.w += v1 * w.w;
                c2.x += v2 * w.x; c2.y += v2 * w.y; c2.z += v2 * w.z; c2.w += v2 * w.w;
                c3.x += v3 * w.x; c3.y += v3 * w.y; c3.z += v3 * w.z; c3.w += v3 * w.w;
            }
            float* hpb = hp + kc * 1024 + rg * 128 + cj;
            *(float4*)(hpb)       = c0;
            *(float4*)(hpb + 128) = c1;
            *(float4*)(hpb + 256) = c2;
            *(float4*)(hpb + 384) = c3;
        }
        __syncthreads();

        // ---- combine G2 chunks -> my partial state; publish to L2 ----
        {
            const float* hb = hp + crow * 128 + cj;
            float4 p0 = *(const float4*)(hb);
            float4 p1 = *(const float4*)(hb + 1024);
            float4 p2 = *(const float4*)(hb + 2048);
            float4 p3 = *(const float4*)(hb + 3072);
            myp = f4add(f4add(p0, p1), f4add(p2, p3));
            __stcg((float4*)&g_pstate[t & 1][gcl][crank][crow][cj], myp);
        }
        __threadfence();
        asm volatile("barrier.cluster.arrive.aligned;" ::: "memory");
        asm volatile("barrier.cluster.wait.aligned;"   ::: "memory");
    }

    // ---- apply final step's state and write out (rank 0 only) ----
    {
        const int pb = (T_STEPS - 1) & 1;
        float4 acc = myp;
        #pragma unroll
        for (int r = 0; r < CSZ; ++r) {
            if (r == crank) continue;
            float4 v = __ldcg((const float4*)&g_pstate[pb][gcl][r][crow][cj]);
            acc = f4add(acc, v);
        }
        float4 av = *(float4*)(a_s + crow * DST + cj);
        av.x += acc.x + rb2.x;  av.y += acc.y + rb2.y;
        av.z += acc.z + rb2.z;  av.w += acc.w + rb2.w;
        if (crank == 0)
            *(float4*)(out + (size_t)(rowbase + crow) * DST + cj) = av;
    }
}

extern "C" void kernel_launch(void* const* d_in, const int* in_sizes, int n_in,
                              void* d_out, int out_size) {
    // metadata order: inputs, a0, W1, b1, W2, b2
    const float* x  = (const float*)d_in[0];
    const float* a0 = (const float*)d_in[1];
    const float* W1 = (const float*)d_in[2];
    const float* b1 = (const float*)d_in[3];
    const float* W2 = (const float*)d_in[4];
    const float* b2 = (const float*)d_in[5];
    float* out = (float*)d_out;

    const size_t smem = SMEM_FLOATS * sizeof(float);   // 221184 B
    cudaFuncSetAttribute(rnn_kernel, cudaFuncAttributeMaxDynamicSharedMemorySize,
                         (int)smem);
    rnn_kernel<<<NCL * CSZ, NTHREADS, smem>>>(x, a0, W1, b1, W2, b2, out);
}

// round 3
// speedup vs baseline: 1.2803x; 1.2803x over previous
#include <cuda_runtime.h>
#include <cstdint>
#include <cstddef>

// ----------------------------------------------------------------------------
// Persistent cluster RNN, round 3:
//   a <- a + W2^T tanh(W1^T [x_t; a] + b1) + b2,  512 steps.
// 32 clusters x 4 CTAs. Cluster owns 8 batch rows; CTA rank owns hidden slice
// [128r, 128r+128) with fp32 W1/W2 slices resident in smem.
// New this round:
//  - packed fma.rn.f32x2 (FFMA2) for all GEMM accumulation (2 FMA / instr)
//  - G1 with 8-rows-per-warp (weight-crossbar dup=1), 2-round smem partial
//    accumulation to keep the partial buffer at 16KB
//  - no __threadfence: rely on barrier.cluster release/acquire semantics
// Cross-CTA state reduction stays in L2 (__stcg/__ldcg), double-buffered.
// ----------------------------------------------------------------------------

#define T_STEPS  512
#define DIN      128
#define DST      128
#define DHID     512
#define NCL      32
#define CSZ      4
#define ROWS     8
#define NTHREADS 256

typedef unsigned long long u64;

// packed f32x2 helpers (sm_103a; ptxas never emits these from C++)
#define FMA2(acc, s, w) asm("fma.rn.f32x2 %0, %1, %2, %0;" : "+l"(acc) : "l"(s), "l"(w))
#define ADD2(d, a)      asm("add.rn.f32x2 %0, %0, %1;"     : "+l"(d)   : "l"(a))
#define PACK2(d, v)     asm("mov.b64 %0, {%1, %1};"        : "=l"(d)   : "r"(__float_as_uint(v)))

// double-buffered per-rank partial states (1 MB static scratch)
__device__ float g_pstate[2][NCL][CSZ][ROWS][DST];

// smem layout (floats):
//   W1s [256][128] @ 0       (131072 B)
//   W2s [128][128] @ 32768   ( 65536 B)
//   hp  [4][8][128]@ 49152   ( 16384 B)   partial buffer (G1 2-round, G2 direct)
//   a_s [8][128]   @ 53248   (  4096 B)
//   x_s [8][128]   @ 54272   (  4096 B)
//   h_s [8][128]   @ 55296   (  4096 B)
#define SMEM_FLOATS 56320    // 225280 bytes

static __device__ __forceinline__ float4 f4add(float4 a, float4 b) {
    return make_float4(a.x + b.x, a.y + b.y, a.z + b.z, a.w + b.w);
}

__global__ void __cluster_dims__(CSZ, 1, 1) __launch_bounds__(NTHREADS, 1)
rnn_kernel(const float* __restrict__ x,  const float* __restrict__ a0,
           const float* __restrict__ W1, const float* __restrict__ b1,
           const float* __restrict__ W2, const float* __restrict__ b2,
           float* __restrict__ out)
{
    extern __shared__ float sm[];
    float* W1s = sm;            // [256][128], row = global k (x: 0..127, a: 128..255)
    float* W2s = sm + 32768;    // [128][128], row = local hidden j
    float* hp  = sm + 49152;    // [4][8][128]
    float* a_s = sm + 53248;    // [8][128]
    float* x_s = sm + 54272;    // [8][128]
    float* h_s = sm + 55296;    // [8][128]

    const int tid   = threadIdx.x;
    const int lane  = tid & 31;
    const int wid   = tid >> 5;
    const int bx    = blockIdx.x;
    const int crank = bx & (CSZ - 1);
    const int gcl   = bx >> 2;
    const int rowbase = gcl * ROWS;
    const int jbase   = crank * 128;

    // ---- prologue: resident weights + initial state + x(0) ----
    for (int i = tid; i < 256 * 32; i += NTHREADS) {           // W1 slice, f4 granules
        int row = i >> 5, c4 = (i & 31) << 2;
        *(float4*)(W1s + row * 128 + c4) =
            *(const float4*)(W1 + row * DHID + jbase + c4);
    }
    for (int i = tid; i < 4096; i += NTHREADS)                 // W2 slice (contiguous)
        ((float4*)W2s)[i] = ((const float4*)(W2 + jbase * DST))[i];
    for (int i = tid; i < 256; i += NTHREADS)
        ((float4*)a_s)[i] = ((const float4*)(a0 + rowbase * DST))[i];
    for (int i = tid; i < 256; i += NTHREADS) {                // x(0)
        int r = i >> 5, c4 = (i & 31) << 2;
        *(float4*)(x_s + r * 128 + c4) =
            *(const float4*)(x + (size_t)(rowbase + r) * (size_t)(T_STEPS * DIN) + c4);
    }

    // combine/publish mapping: warp = row, lane = 4 consecutive cols
    const int crow = wid;
    const int cj   = lane * 4;
    const float4 rb1 = *(const float4*)(b1 + jbase + cj);
    const float4 rb2 = *(const float4*)(b2 + cj);

    // G1 mapping: warp = K-chunk (32 k), all 8 rows  -> dup=1 weight traffic
    const float* g1_act = (wid < 4) ? (x_s + wid * 32) : (a_s + (wid - 4) * 32);
    const float* g1_wr  = W1s + (wid * 32) * 128 + cj;
    float* g1_hpb = hp + (wid & 3) * 1024 + cj;

    // G2 mapping: warp = (row-group of 4, K-chunk of 32)
    const int rg2 = (wid & 1) * 4;
    const int kc2 = wid >> 1;
    const float* g2_wr = W2s + (kc2 * 32) * 128 + cj;

    const float* xrow = x + (size_t)(rowbase + crow) * (size_t)(T_STEPS * DIN) + cj;

    float4 myp = make_float4(0.f, 0.f, 0.f, 0.f);
    float4 xr  = make_float4(0.f, 0.f, 0.f, 0.f);   // holds x(t+1) at iteration t stage 1

    __syncthreads();

    for (int t = 0; t < T_STEPS; ++t) {
        // ---- stage 1: apply step t-1 state; stage x(t) ----
        if (t > 0) {
            const int pb = (t - 1) & 1;
            float4 acc = myp;
            #pragma unroll
            for (int r = 0; r < CSZ; ++r) {
                if (r == crank) continue;
                acc = f4add(acc, __ldcg((const float4*)&g_pstate[pb][gcl][r][crow][cj]));
            }
            float4 av = *(float4*)(a_s + crow * DST + cj);
            av.x += acc.x + rb2.x;  av.y += acc.y + rb2.y;
            av.z += acc.z + rb2.z;  av.w += acc.w + rb2.w;
            *(float4*)(a_s + crow * DST + cj) = av;
            *(float4*)(x_s + crow * DIN + cj) = xr;   // x(t)
        }
        __syncthreads();

        // ---- G1: preact partials, warp = 32-k chunk, 8 rows, packed FMA ----
        {
            ulonglong2 acc[ROWS];
            #pragma unroll
            for (int r = 0; r < ROWS; ++r) { acc[r].x = 0ull; acc[r].y = 0ull; }
            #pragma unroll
            for (int kb = 0; kb < 8; ++kb) {
                float4 av[ROWS];
                #pragma unroll
                for (int r = 0; r < ROWS; ++r)
                    av[r] = *(const float4*)(g1_act + r * 128 + kb * 4);
                const float* wk = g1_wr + kb * 4 * 128;
                #pragma unroll
                for (int kk = 0; kk < 4; ++kk) {
                    ulonglong2 w = *(const ulonglong2*)(wk + kk * 128);
                    #pragma unroll
                    for (int r = 0; r < ROWS; ++r) {
                        float s = (kk == 0) ? av[r].x : (kk == 1) ? av[r].y
                                : (kk == 2) ? av[r].z : av[r].w;
                        u64 sp; PACK2(sp, s);
                        FMA2(acc[r].x, sp, w.x);
                        FMA2(acc[r].y, sp, w.y);
                    }
                }
            }
            // 2-round accumulation into hp[wid&3]
            if (wid < 4) {
                #pragma unroll
                for (int r = 0; r < ROWS; ++r)
                    *(ulonglong2*)(g1_hpb + r * 128) = acc[r];
            }
            __syncthreads();
            if (wid >= 4) {
                #pragma unroll
                for (int r = 0; r < ROWS; ++r) {
                    ulonglong2 cur = *(ulonglong2*)(g1_hpb + r * 128);
                    ADD2(cur.x, acc[r].x);
                    ADD2(cur.y, acc[r].y);
                    *(ulonglong2*)(g1_hpb + r * 128) = cur;
                }
            }
            __syncthreads();
        }

        // ---- combine + bias + tanh -> h_s ----
        {
            const float* hb = hp + crow * 128 + cj;
            float4 p0 = *(const float4*)(hb);
            float4 p1 = *(const float4*)(hb + 1024);
            float4 p2 = *(const float4*)(hb + 2048);
            float4 p3 = *(const float4*)(hb + 3072);
            float4 hv;
            hv.x = tanhf(p0.x + p1.x + p2.x + p3.x + rb1.x);
            hv.y = tanhf(p0.y + p1.y + p2.y + p3.y + rb1.y);
            hv.z = tanhf(p0.z + p1.z + p2.z + p3.z + rb1.z);
            hv.w = tanhf(p0.w + p1.w + p2.w + p3.w + rb1.w);
            *(float4*)(h_s + crow * 128 + cj) = hv;
        }
        __syncthreads();

        // ---- G2: state partials, warp = (4 rows, 32 k), packed FMA ----
        {
            ulonglong2 acc[4];
            #pragma unroll
            for (int r = 0; r < 4; ++r) { acc[r].x = 0ull; acc[r].y = 0ull; }
            const float* act2 = h_s + rg2 * 128 + kc2 * 32;
            #pragma unroll
            for (int kb = 0; kb < 8; ++kb) {
                float4 av[4];
                #pragma unroll
                for (int r = 0; r < 4; ++r)
                    av[r] = *(const float4*)(act2 + r * 128 + kb * 4);
                const float* wk = g2_wr + kb * 4 * 128;
                #pragma unroll
                for (int kk = 0; kk < 4; ++kk) {
                    ulonglong2 w = *(const ulonglong2*)(wk + kk * 128);
                    #pragma unroll
                    for (int r = 0; r < 4; ++r) {
                        float s = (kk == 0) ? av[r].x : (kk == 1) ? av[r].y
                                : (kk == 2) ? av[r].z : av[r].w;
                        u64 sp; PACK2(sp, s);
                        FMA2(acc[r].x, sp, w.x);
                        FMA2(acc[r].y, sp, w.y);
                    }
                }
            }
            float* hpo = hp + kc2 * 1024 + rg2 * 128 + cj;
            #pragma unroll
            for (int r = 0; r < 4; ++r)
                *(ulonglong2*)(hpo + r * 128) = acc[r];
        }
        __syncthreads();

        // ---- combine G2 -> my partial state; publish via L2; prefetch x ----
        {
            const float* hb = hp + crow * 128 + cj;
            float4 q0 = *(const float4*)(hb);
            float4 q1 = *(const float4*)(hb + 1024);
            float4 q2 = *(const float4*)(hb + 2048);
            float4 q3 = *(const float4*)(hb + 3072);
            myp = f4add(f4add(q0, q1), f4add(q2, q3));
            __stcg((float4*)&g_pstate[t & 1][gcl][crank][crow][cj], myp);
            if (t + 1 < T_STEPS)
                xr = *(const float4*)(xrow + (size_t)(t + 1) * DIN);
        }
        // release/acquire cluster barrier orders the .cg exchange (no fence)
        asm volatile("barrier.cluster.arrive.aligned;" ::: "memory");
        asm volatile("barrier.cluster.wait.aligned;"   ::: "memory");
    }

    // ---- epilogue: apply final state; rank 0 writes out ----
    {
        const int pb = (T_STEPS - 1) & 1;
        float4 acc = myp;
        #pragma unroll
        for (int r = 0; r < CSZ; ++r) {
            if (r == crank) continue;
            acc = f4add(acc, __ldcg((const float4*)&g_pstate[pb][gcl][r][crow][cj]));
        }
        float4 av = *(float4*)(a_s + crow * DST + cj);
        av.x += acc.x + rb2.x;  av.y += acc.y + rb2.y;
        av.z += acc.z + rb2.z;  av.w += acc.w + rb2.w;
        if (crank == 0)
            *(float4*)(out + (size_t)(rowbase + crow) * DST + cj) = av;
    }
}

extern "C" void kernel_launch(void* const* d_in, const int* in_sizes, int n_in,
                              void* d_out, int out_size) {
    const float* x  = (const float*)d_in[0];
    const float* a0 = (const float*)d_in[1];
    const float* W1 = (const float*)d_in[2];
    const float* b1 = (const float*)d_in[3];
    const float* W2 = (const float*)d_in[4];
    const float* b2 = (const float*)d_in[5];
    float* out = (float*)d_out;

    const size_t smem = SMEM_FLOATS * sizeof(float);   // 225280 B
    cudaFuncSetAttribute(rnn_kernel, cudaFuncAttributeMaxDynamicSharedMemorySize,
                         (int)smem);
    rnn_kernel<<<NCL * CSZ, NTHREADS, smem>>>(x, a0, W1, b1, W2, b2, out);
}